// round 11
// baseline (speedup 1.0000x reference)
#include <cuda_runtime.h>
#include <cstdint>

// LIF neuron scan: x[T=8, B, C, H, W] fp32 -> spikes {-1,0,+1} fp32.
// tau = 5/3; V' = V + (-V/tau + x); spike if |V'| >= 1; hard reset to 0.
//
// R11: compile-time slab offsets. Shape is fixed (n_spatial = 4,194,304),
// so the kernel is templated on NSPATIAL: all 16 per-thread slab offsets
// become immediate fields in LDG/STG (base + imm), removing ~32 IMAD/LEA
// integer ops per thread. Generic fallback kernel covers any other shape.
// Body = R10 (best, 43.5us, rel_err 0): 256-bit LDG/STG, packed f32x2
// bit-exact Markstein recurrence, predicate-free clamp/trunc spike.

static constexpr int T_STEPS = 8;
static constexpr int VEC = 8;                  // floats per 256-bit access
static constexpr int NS_EXPECTED = 4194304;    // B*C*H*W for this problem

using u64 = unsigned long long;

__device__ __forceinline__ void ldg256(const float* p, float v[VEC]) {
    asm volatile("ld.global.v8.b32 {%0,%1,%2,%3,%4,%5,%6,%7}, [%8];"
                 : "=f"(v[0]), "=f"(v[1]), "=f"(v[2]), "=f"(v[3]),
                   "=f"(v[4]), "=f"(v[5]), "=f"(v[6]), "=f"(v[7])
                 : "l"(p));
}

__device__ __forceinline__ void stg256(float* p, const float v[VEC]) {
    asm volatile("st.global.v8.b32 [%0], {%1,%2,%3,%4,%5,%6,%7,%8};"
                 :: "l"(p),
                    "f"(v[0]), "f"(v[1]), "f"(v[2]), "f"(v[3]),
                    "f"(v[4]), "f"(v[5]), "f"(v[6]), "f"(v[7])
                 : "memory");
}

__device__ __forceinline__ u64 f32x2_pack(float lo, float hi) {
    u64 r;
    asm("mov.b64 %0, {%1, %2};" : "=l"(r) : "f"(lo), "f"(hi));
    return r;
}
__device__ __forceinline__ void f32x2_unpack(u64 v, float& lo, float& hi) {
    asm("mov.b64 {%0, %1}, %2;" : "=f"(lo), "=f"(hi) : "l"(v));
}

// Per-lane, identical to the scalar RN sequence:
//   q0=V*R; e=fma(-TAU,q0,V); q=fma(e,R,q0)   [Markstein: q = RN(V/TAU)]
//   dv=fma(q,-1,x)=RN(x-q);   vn=RN(V+dv)
__device__ __forceinline__ u64 lif_vn_pair(u64 Vp, u64 xp,
                                           u64 R2, u64 nT2, u64 m1) {
    u64 q0, e, q, dv, vn;
    asm("mul.rn.f32x2 %0, %1, %2;"     : "=l"(q0) : "l"(Vp), "l"(R2));
    asm("fma.rn.f32x2 %0, %1, %2, %3;" : "=l"(e)  : "l"(nT2), "l"(q0), "l"(Vp));
    asm("fma.rn.f32x2 %0, %1, %2, %3;" : "=l"(q)  : "l"(e),  "l"(R2), "l"(q0));
    asm("fma.rn.f32x2 %0, %1, %2, %3;" : "=l"(dv) : "l"(q),  "l"(m1), "l"(xp));
    asm("add.rn.f32x2 %0, %1, %2;"     : "=l"(vn) : "l"(Vp), "l"(dv));
    return vn;
}

// o = trunc(clamp(vn,-1,1)): exactly (vn>=1)-(vn<=-1), no predicates.
__device__ __forceinline__ float spike_out(float vn) {
    float c = fminf(fmaxf(vn, -1.0f), 1.0f);   // 2x FMNMX (alu pipe)
    return truncf(c);                          // FRND (conversion pipe)
}

template <int NSPATIAL>
__device__ __forceinline__ void lif_body(const float* __restrict__ xp,
                                         float* __restrict__ yp) {
    constexpr float TAU = 5.0f / 3.0f;     // fl(5/3), matches jnp float32
    constexpr float R   = 1.0f / TAU;      // RN(1/fl(5/3)), compile-time
    const u64 R2  = f32x2_pack(R, R);
    const u64 nT2 = f32x2_pack(-TAU, -TAU);
    const u64 m1  = f32x2_pack(-1.0f, -1.0f);

    // Batched prefetch: 8 independent LDG.E.256 in flight; slab offsets
    // are compile-time immediates (t * NSPATIAL).
    float xs[T_STEPS][VEC];
#pragma unroll
    for (int t = 0; t < T_STEPS; ++t)
        ldg256(xp + (size_t)t * NSPATIAL, xs[t]);

    u64 V[VEC / 2];
#pragma unroll
    for (int k = 0; k < VEC / 2; ++k) V[k] = 0ull;

#pragma unroll
    for (int t = 0; t < T_STEPS; ++t) {
        float o[VEC];
#pragma unroll
        for (int k = 0; k < VEC / 2; ++k) {
            u64 xpair = f32x2_pack(xs[t][2 * k], xs[t][2 * k + 1]);
            u64 vn = lif_vn_pair(V[k], xpair, R2, nT2, m1);

            float v0, v1;
            f32x2_unpack(vn, v0, v1);
            o[2 * k]     = spike_out(v0);
            o[2 * k + 1] = spike_out(v1);

            // V = vn - o^2 * vn   (o^2 in {0,1} exact -> 0 on spike, vn else)
            u64 o2  = f32x2_pack(o[2 * k], o[2 * k + 1]);
            u64 oo, nvn, Vn;
            asm("mul.rn.f32x2 %0, %1, %2;"     : "=l"(oo)  : "l"(o2), "l"(o2));
            asm("mul.rn.f32x2 %0, %1, %2;"     : "=l"(nvn) : "l"(vn), "l"(m1));
            asm("fma.rn.f32x2 %0, %1, %2, %3;" : "=l"(Vn)  : "l"(oo), "l"(nvn), "l"(vn));
            V[k] = Vn;
        }
        stg256(yp + (size_t)t * NSPATIAL, o);   // STG.E.256, imm offset
    }
}

template <int NSPATIAL>
__global__ __launch_bounds__(256)
void lif_kernel_fixed(const float* __restrict__ x, float* __restrict__ y,
                      int n8) {
    int i = blockIdx.x * blockDim.x + threadIdx.x;
    if (i >= n8) return;
    lif_body<NSPATIAL>(x + (size_t)i * VEC, y + (size_t)i * VEC);
}

// Generic fallback (runtime n_spatial) — same body structure.
__global__ __launch_bounds__(256)
void lif_kernel_generic(const float* __restrict__ x, float* __restrict__ y,
                        int n8, int n_spatial) {
    int i = blockIdx.x * blockDim.x + threadIdx.x;
    if (i >= n8) return;

    const float* xp = x + (size_t)i * VEC;
    float*       yp = y + (size_t)i * VEC;

    constexpr float TAU = 5.0f / 3.0f;
    constexpr float R   = 1.0f / TAU;
    const u64 R2  = f32x2_pack(R, R);
    const u64 nT2 = f32x2_pack(-TAU, -TAU);
    const u64 m1  = f32x2_pack(-1.0f, -1.0f);

    float xs[T_STEPS][VEC];
#pragma unroll
    for (int t = 0; t < T_STEPS; ++t)
        ldg256(xp + (size_t)t * n_spatial, xs[t]);

    u64 V[VEC / 2];
#pragma unroll
    for (int k = 0; k < VEC / 2; ++k) V[k] = 0ull;

#pragma unroll
    for (int t = 0; t < T_STEPS; ++t) {
        float o[VEC];
#pragma unroll
        for (int k = 0; k < VEC / 2; ++k) {
            u64 xpair = f32x2_pack(xs[t][2 * k], xs[t][2 * k + 1]);
            u64 vn = lif_vn_pair(V[k], xpair, R2, nT2, m1);
            float v0, v1;
            f32x2_unpack(vn, v0, v1);
            o[2 * k]     = spike_out(v0);
            o[2 * k + 1] = spike_out(v1);
            u64 o2  = f32x2_pack(o[2 * k], o[2 * k + 1]);
            u64 oo, nvn, Vn;
            asm("mul.rn.f32x2 %0, %1, %2;"     : "=l"(oo)  : "l"(o2), "l"(o2));
            asm("mul.rn.f32x2 %0, %1, %2;"     : "=l"(nvn) : "l"(vn), "l"(m1));
            asm("fma.rn.f32x2 %0, %1, %2, %3;" : "=l"(Vn)  : "l"(oo), "l"(nvn), "l"(vn));
            V[k] = Vn;
        }
        stg256(yp + (size_t)t * n_spatial, o);
    }
}

extern "C" void kernel_launch(void* const* d_in, const int* in_sizes, int n_in,
                              void* d_out, int out_size) {
    const float* x = (const float*)d_in[0];
    float* y = (float*)d_out;

    int total = in_sizes[0];          // T*B*C*H*W = 33,554,432
    int n_spatial = total / T_STEPS;  // 4,194,304
    int n8 = n_spatial / VEC;         // 524,288 threads (8 floats each)

    int threads = 256;
    int blocks = (n8 + threads - 1) / threads;

    if (n_spatial == NS_EXPECTED) {
        lif_kernel_fixed<NS_EXPECTED><<<blocks, threads>>>(x, y, n8);
    } else {
        lif_kernel_generic<<<blocks, threads>>>(x, y, n8, n_spatial);
    }
}

// round 12
// speedup vs baseline: 1.0116x; 1.0116x over previous
#include <cuda_runtime.h>
#include <cstdint>

// LIF neuron scan: x[T=8, B, C, H, W] fp32 -> spikes {-1,0,+1} fp32.
// tau = 5/3; V' = V + (-V/tau + x); spike if |V'| >= 1; hard reset to 0.
//
// FINAL (= R10, series best 43.49us): minimum-dynamic-instruction kernel
// against the sustained-DVFS HBM ceiling (~6 TB/s timed loop; kernel
// demonstrates 7.4 TB/s / 93% of spec at unconstrained clocks under ncu).
//  - 256-bit LDG/STG (v8.b32): minimum memory instruction count.
//  - packed f32x2 Markstein div-by-const recurrence: bit-identical per
//    lane to IEEE RN division for normal operands (rel_err 0.0 measured).
//  - predicate-free spike: o = trunc(clamp(vn,-1,1)) == (vn>=1)-(vn<=-1),
//    V = fma(o^2, -vn, vn) == spiked ? 0 : vn. No FSETP/FSEL in hot path.
// Levers measured non-binding in R2-R11: occupancy (30-83%), issue rate,
// wave/grid shape, persistent CTAs, L2 eviction policy, imm addressing.

static constexpr int T_STEPS = 8;
static constexpr int VEC = 8;                  // floats per 256-bit access

using u64 = unsigned long long;

__device__ __forceinline__ void ldg256(const float* p, float v[VEC]) {
    asm volatile("ld.global.v8.b32 {%0,%1,%2,%3,%4,%5,%6,%7}, [%8];"
                 : "=f"(v[0]), "=f"(v[1]), "=f"(v[2]), "=f"(v[3]),
                   "=f"(v[4]), "=f"(v[5]), "=f"(v[6]), "=f"(v[7])
                 : "l"(p));
}

__device__ __forceinline__ void stg256(float* p, const float v[VEC]) {
    asm volatile("st.global.v8.b32 [%0], {%1,%2,%3,%4,%5,%6,%7,%8};"
                 :: "l"(p),
                    "f"(v[0]), "f"(v[1]), "f"(v[2]), "f"(v[3]),
                    "f"(v[4]), "f"(v[5]), "f"(v[6]), "f"(v[7])
                 : "memory");
}

__device__ __forceinline__ u64 f32x2_pack(float lo, float hi) {
    u64 r;
    asm("mov.b64 %0, {%1, %2};" : "=l"(r) : "f"(lo), "f"(hi));
    return r;
}
__device__ __forceinline__ void f32x2_unpack(u64 v, float& lo, float& hi) {
    asm("mov.b64 {%0, %1}, %2;" : "=f"(lo), "=f"(hi) : "l"(v));
}

// Per-lane, identical to the scalar RN sequence:
//   q0=V*R; e=fma(-TAU,q0,V); q=fma(e,R,q0)   [Markstein: q = RN(V/TAU)]
//   dv=fma(q,-1,x)=RN(x-q);   vn=RN(V+dv)
__device__ __forceinline__ u64 lif_vn_pair(u64 Vp, u64 xp,
                                           u64 R2, u64 nT2, u64 m1) {
    u64 q0, e, q, dv, vn;
    asm("mul.rn.f32x2 %0, %1, %2;"     : "=l"(q0) : "l"(Vp), "l"(R2));
    asm("fma.rn.f32x2 %0, %1, %2, %3;" : "=l"(e)  : "l"(nT2), "l"(q0), "l"(Vp));
    asm("fma.rn.f32x2 %0, %1, %2, %3;" : "=l"(q)  : "l"(e),  "l"(R2), "l"(q0));
    asm("fma.rn.f32x2 %0, %1, %2, %3;" : "=l"(dv) : "l"(q),  "l"(m1), "l"(xp));
    asm("add.rn.f32x2 %0, %1, %2;"     : "=l"(vn) : "l"(Vp), "l"(dv));
    return vn;
}

// o = trunc(clamp(vn,-1,1)): exactly (vn>=1)-(vn<=-1), no predicates.
__device__ __forceinline__ float spike_out(float vn) {
    float c = fminf(fmaxf(vn, -1.0f), 1.0f);   // 2x FMNMX (alu pipe)
    return truncf(c);                          // FRND (conversion pipe)
}

__global__ __launch_bounds__(256)
void lif_kernel(const float* __restrict__ x, float* __restrict__ y,
                int n8, int n_spatial) {
    int i = blockIdx.x * blockDim.x + threadIdx.x;
    if (i >= n8) return;

    constexpr float TAU = 5.0f / 3.0f;     // fl(5/3), matches jnp float32
    constexpr float R   = 1.0f / TAU;      // RN(1/fl(5/3)), compile-time
    const u64 R2  = f32x2_pack(R, R);
    const u64 nT2 = f32x2_pack(-TAU, -TAU);
    const u64 m1  = f32x2_pack(-1.0f, -1.0f);

    const float* xp = x + (size_t)i * VEC;
    float*       yp = y + (size_t)i * VEC;

    // Batched prefetch: 8 independent LDG.E.256 in flight.
    float xs[T_STEPS][VEC];
#pragma unroll
    for (int t = 0; t < T_STEPS; ++t)
        ldg256(xp + (size_t)t * n_spatial, xs[t]);

    u64 V[VEC / 2];
#pragma unroll
    for (int k = 0; k < VEC / 2; ++k) V[k] = 0ull;

#pragma unroll
    for (int t = 0; t < T_STEPS; ++t) {
        float o[VEC];
#pragma unroll
        for (int k = 0; k < VEC / 2; ++k) {
            u64 xpair = f32x2_pack(xs[t][2 * k], xs[t][2 * k + 1]);
            u64 vn = lif_vn_pair(V[k], xpair, R2, nT2, m1);

            float v0, v1;
            f32x2_unpack(vn, v0, v1);
            o[2 * k]     = spike_out(v0);
            o[2 * k + 1] = spike_out(v1);

            // V = vn - o^2 * vn   (o^2 in {0,1} exact -> 0 on spike, vn else)
            u64 o2  = f32x2_pack(o[2 * k], o[2 * k + 1]);
            u64 oo, nvn, Vn;
            asm("mul.rn.f32x2 %0, %1, %2;"     : "=l"(oo)  : "l"(o2), "l"(o2));
            asm("mul.rn.f32x2 %0, %1, %2;"     : "=l"(nvn) : "l"(vn), "l"(m1));
            asm("fma.rn.f32x2 %0, %1, %2, %3;" : "=l"(Vn)  : "l"(oo), "l"(nvn), "l"(vn));
            V[k] = Vn;
        }
        stg256(yp + (size_t)t * n_spatial, o);   // STG.E.256
    }
}

extern "C" void kernel_launch(void* const* d_in, const int* in_sizes, int n_in,
                              void* d_out, int out_size) {
    const float* x = (const float*)d_in[0];
    float* y = (float*)d_out;

    int total = in_sizes[0];          // T*B*C*H*W = 33,554,432
    int n_spatial = total / T_STEPS;  // 4,194,304
    int n8 = n_spatial / VEC;         // 524,288 threads (8 floats each)

    int threads = 256;
    int blocks = (n8 + threads - 1) / threads;
    lif_kernel<<<blocks, threads>>>(x, y, n8, n_spatial);
}

// round 13
// speedup vs baseline: 1.0258x; 1.0140x over previous
#include <cuda_runtime.h>
#include <cstdint>

// LIF neuron scan: x[T=8, B, C, H, W] fp32 -> spikes {-1,0,+1} fp32.
// tau = 5/3; V' = V + (-V/tau + x); spike if |V'| >= 1; hard reset to 0.
//
// R13: R10 body (series best, 43.5us) with 512-thread CTAs — the one
// untested configuration dimension. Halves CTA count (1024), doubles
// per-CTA contiguous footprint (16KB/slab), lengthens drain/fill overlap
// at wave boundaries (R5 showed wave phasing moves the needle ~1-2us).
//  - 256-bit LDG/STG (v8.b32): minimum memory instruction count.
//  - packed f32x2 Markstein div-by-const recurrence: bit-identical per
//    lane to IEEE RN division for normal operands (rel_err 0.0 measured).
//  - predicate-free spike: o = trunc(clamp(vn,-1,1)) == (vn>=1)-(vn<=-1),
//    V = fma(o^2, -vn, vn) == spiked ? 0 : vn.

static constexpr int T_STEPS = 8;
static constexpr int VEC = 8;                  // floats per 256-bit access

using u64 = unsigned long long;

__device__ __forceinline__ void ldg256(const float* p, float v[VEC]) {
    asm volatile("ld.global.v8.b32 {%0,%1,%2,%3,%4,%5,%6,%7}, [%8];"
                 : "=f"(v[0]), "=f"(v[1]), "=f"(v[2]), "=f"(v[3]),
                   "=f"(v[4]), "=f"(v[5]), "=f"(v[6]), "=f"(v[7])
                 : "l"(p));
}

__device__ __forceinline__ void stg256(float* p, const float v[VEC]) {
    asm volatile("st.global.v8.b32 [%0], {%1,%2,%3,%4,%5,%6,%7,%8};"
                 :: "l"(p),
                    "f"(v[0]), "f"(v[1]), "f"(v[2]), "f"(v[3]),
                    "f"(v[4]), "f"(v[5]), "f"(v[6]), "f"(v[7])
                 : "memory");
}

__device__ __forceinline__ u64 f32x2_pack(float lo, float hi) {
    u64 r;
    asm("mov.b64 %0, {%1, %2};" : "=l"(r) : "f"(lo), "f"(hi));
    return r;
}
__device__ __forceinline__ void f32x2_unpack(u64 v, float& lo, float& hi) {
    asm("mov.b64 {%0, %1}, %2;" : "=f"(lo), "=f"(hi) : "l"(v));
}

// Per-lane, identical to the scalar RN sequence:
//   q0=V*R; e=fma(-TAU,q0,V); q=fma(e,R,q0)   [Markstein: q = RN(V/TAU)]
//   dv=fma(q,-1,x)=RN(x-q);   vn=RN(V+dv)
__device__ __forceinline__ u64 lif_vn_pair(u64 Vp, u64 xp,
                                           u64 R2, u64 nT2, u64 m1) {
    u64 q0, e, q, dv, vn;
    asm("mul.rn.f32x2 %0, %1, %2;"     : "=l"(q0) : "l"(Vp), "l"(R2));
    asm("fma.rn.f32x2 %0, %1, %2, %3;" : "=l"(e)  : "l"(nT2), "l"(q0), "l"(Vp));
    asm("fma.rn.f32x2 %0, %1, %2, %3;" : "=l"(q)  : "l"(e),  "l"(R2), "l"(q0));
    asm("fma.rn.f32x2 %0, %1, %2, %3;" : "=l"(dv) : "l"(q),  "l"(m1), "l"(xp));
    asm("add.rn.f32x2 %0, %1, %2;"     : "=l"(vn) : "l"(Vp), "l"(dv));
    return vn;
}

// o = trunc(clamp(vn,-1,1)): exactly (vn>=1)-(vn<=-1), no predicates.
__device__ __forceinline__ float spike_out(float vn) {
    float c = fminf(fmaxf(vn, -1.0f), 1.0f);   // 2x FMNMX (alu pipe)
    return truncf(c);                          // FRND (conversion pipe)
}

__global__ __launch_bounds__(512)
void lif_kernel(const float* __restrict__ x, float* __restrict__ y,
                int n8, int n_spatial) {
    int i = blockIdx.x * blockDim.x + threadIdx.x;
    if (i >= n8) return;

    constexpr float TAU = 5.0f / 3.0f;     // fl(5/3), matches jnp float32
    constexpr float R   = 1.0f / TAU;      // RN(1/fl(5/3)), compile-time
    const u64 R2  = f32x2_pack(R, R);
    const u64 nT2 = f32x2_pack(-TAU, -TAU);
    const u64 m1  = f32x2_pack(-1.0f, -1.0f);

    const float* xp = x + (size_t)i * VEC;
    float*       yp = y + (size_t)i * VEC;

    // Batched prefetch: 8 independent LDG.E.256 in flight.
    float xs[T_STEPS][VEC];
#pragma unroll
    for (int t = 0; t < T_STEPS; ++t)
        ldg256(xp + (size_t)t * n_spatial, xs[t]);

    u64 V[VEC / 2];
#pragma unroll
    for (int k = 0; k < VEC / 2; ++k) V[k] = 0ull;

#pragma unroll
    for (int t = 0; t < T_STEPS; ++t) {
        float o[VEC];
#pragma unroll
        for (int k = 0; k < VEC / 2; ++k) {
            u64 xpair = f32x2_pack(xs[t][2 * k], xs[t][2 * k + 1]);
            u64 vn = lif_vn_pair(V[k], xpair, R2, nT2, m1);

            float v0, v1;
            f32x2_unpack(vn, v0, v1);
            o[2 * k]     = spike_out(v0);
            o[2 * k + 1] = spike_out(v1);

            // V = vn - o^2 * vn   (o^2 in {0,1} exact -> 0 on spike, vn else)
            u64 o2  = f32x2_pack(o[2 * k], o[2 * k + 1]);
            u64 oo, nvn, Vn;
            asm("mul.rn.f32x2 %0, %1, %2;"     : "=l"(oo)  : "l"(o2), "l"(o2));
            asm("mul.rn.f32x2 %0, %1, %2;"     : "=l"(nvn) : "l"(vn), "l"(m1));
            asm("fma.rn.f32x2 %0, %1, %2, %3;" : "=l"(Vn)  : "l"(oo), "l"(nvn), "l"(vn));
            V[k] = Vn;
        }
        stg256(yp + (size_t)t * n_spatial, o);   // STG.E.256
    }
}

extern "C" void kernel_launch(void* const* d_in, const int* in_sizes, int n_in,
                              void* d_out, int out_size) {
    const float* x = (const float*)d_in[0];
    float* y = (float*)d_out;

    int total = in_sizes[0];          // T*B*C*H*W = 33,554,432
    int n_spatial = total / T_STEPS;  // 4,194,304
    int n8 = n_spatial / VEC;         // 524,288 threads (8 floats each)

    int threads = 512;
    int blocks = (n8 + threads - 1) / threads;
    lif_kernel<<<blocks, threads>>>(x, y, n8, n_spatial);
}